// round 5
// baseline (speedup 1.0000x reference)
#include <cuda_runtime.h>

// Shapes (fixed by the problem)
#define BSZ      4
#define MAX_LEN  256
#define IN_DIM   1024
#define BIAFF    512
#define OUTC     512
#define NHEAD    4
#define HD       128   // per-head dim (both in and out)

// Scratch in device globals (no allocations allowed in kernel_launch).
__device__ float g_h[BSZ * MAX_LEN * BIAFF];                         // 2 MB
__device__ float g_v[BSZ * MAX_LEN * BIAFF];                         // 2 MB
__device__ float g_T[(size_t)BSZ * NHEAD * MAX_LEN * HD * HD];       // 256 MB

// ---------------------------------------------------------------------------
// Generic 128x128 tile GEMM, C[i,j] = sum_k A[i,k] * B[.,.]
//   A layout: A[i*lda + k]            (k contiguous)  -- all callers
//   B layout: B_KFAST ? B[j*ldb + k]  (k contiguous)
//                     : B[k*ldb + j]  (j contiguous)
//   C layout: C[i*ldc + j]
// 256 threads, 8x8 accumulators per thread, K-chunks of 16.
// Optional epilogue: +bias[j0+j], LeakyReLU(0.01).
// ---------------------------------------------------------------------------
template <bool B_KFAST, bool DO_EPI>
__device__ __forceinline__ void gemm_tile_128(
    const float* __restrict__ A, int lda,
    const float* __restrict__ B, int ldb,
    float*       __restrict__ C, int ldc,
    int K,
    const float* __restrict__ bias, int j0)
{
    __shared__ float As[16][128];
    __shared__ float Bs[16][128];

    const int tid = threadIdx.x;
    const int tx  = tid & 15;
    const int ty  = tid >> 4;

    // loader indexing (k-fast operands): 2 float4 per thread
    const int ar = tid >> 1;           // row 0..127
    const int ak = (tid & 1) * 8;      // k offset 0 or 8
    // loader indexing (j-fast B): 2 float4 per thread
    const int bk = tid >> 4;           // k row 0..15
    const int bj = (tid & 15) * 8;     // col 0..120

    float acc[8][8];
#pragma unroll
    for (int i = 0; i < 8; i++)
#pragma unroll
        for (int j = 0; j < 8; j++) acc[i][j] = 0.0f;

    for (int k0 = 0; k0 < K; k0 += 16) {
        // ---- stage tiles through registers into smem ----
        float4 av0 = *(const float4*)(A + (size_t)ar * lda + k0 + ak);
        float4 av1 = *(const float4*)(A + (size_t)ar * lda + k0 + ak + 4);
        float4 bv0, bv1;
        if (B_KFAST) {
            bv0 = *(const float4*)(B + (size_t)ar * ldb + k0 + ak);
            bv1 = *(const float4*)(B + (size_t)ar * ldb + k0 + ak + 4);
        } else {
            bv0 = *(const float4*)(B + (size_t)(k0 + bk) * ldb + bj);
            bv1 = *(const float4*)(B + (size_t)(k0 + bk) * ldb + bj + 4);
        }

        // transpose-store A (k-fast -> As[k][i])
        As[ak + 0][ar] = av0.x;  As[ak + 1][ar] = av0.y;
        As[ak + 2][ar] = av0.z;  As[ak + 3][ar] = av0.w;
        As[ak + 4][ar] = av1.x;  As[ak + 5][ar] = av1.y;
        As[ak + 6][ar] = av1.z;  As[ak + 7][ar] = av1.w;
        if (B_KFAST) {
            Bs[ak + 0][ar] = bv0.x;  Bs[ak + 1][ar] = bv0.y;
            Bs[ak + 2][ar] = bv0.z;  Bs[ak + 3][ar] = bv0.w;
            Bs[ak + 4][ar] = bv1.x;  Bs[ak + 5][ar] = bv1.y;
            Bs[ak + 6][ar] = bv1.z;  Bs[ak + 7][ar] = bv1.w;
        } else {
            *(float4*)&Bs[bk][bj]     = bv0;
            *(float4*)&Bs[bk][bj + 4] = bv1;
        }
        __syncthreads();

        // ---- compute 16 k-steps ----
#pragma unroll 8
        for (int kk = 0; kk < 16; kk++) {
            float a[8], bb[8];
            *(float4*)&a[0]  = *(const float4*)&As[kk][ty * 8];
            *(float4*)&a[4]  = *(const float4*)&As[kk][ty * 8 + 4];
            *(float4*)&bb[0] = *(const float4*)&Bs[kk][tx * 8];
            *(float4*)&bb[4] = *(const float4*)&Bs[kk][tx * 8 + 4];
#pragma unroll
            for (int i = 0; i < 8; i++)
#pragma unroll
                for (int j = 0; j < 8; j++)
                    acc[i][j] += a[i] * bb[j];
        }
        __syncthreads();
    }

    // ---- epilogue ----
    const int row0 = ty * 8;
    const int col0 = tx * 8;
#pragma unroll
    for (int i = 0; i < 8; i++) {
        float vals[8];
#pragma unroll
        for (int j = 0; j < 8; j++) {
            float z = acc[i][j];
            if (DO_EPI) {
                z += bias[j0 + col0 + j];
                z = (z > 0.0f) ? z : 0.01f * z;
            }
            vals[j] = z;
        }
        float4* p = (float4*)(C + (size_t)(row0 + i) * ldc + col0);
        p[0] = make_float4(vals[0], vals[1], vals[2], vals[3]);
        p[1] = make_float4(vals[4], vals[5], vals[6], vals[7]);
    }
}

// ---------------------------------------------------------------------------
// K1: h = LeakyReLU(x @ Wh^T + bh), v = LeakyReLU(x @ Wv^T + bv)
// x viewed as [1024, 1024]; Wh/Wv are [512, 1024] (o-major, d contiguous).
// grid = (4 n-tiles, 8 m-tiles, 2 {h,v})
// ---------------------------------------------------------------------------
__global__ __launch_bounds__(256, 2)
void k_mlp(const float* __restrict__ x,
           const float* __restrict__ Wh, const float* __restrict__ bh,
           const float* __restrict__ Wv, const float* __restrict__ bv)
{
    const int nt = blockIdx.x;      // col tile (output feature / 128)
    const int mt = blockIdx.y;      // row tile ((b*l) / 128)
    const int which = blockIdx.z;   // 0 -> h, 1 -> v
    const float* Wm = which ? Wv : Wh;
    const float* bb = which ? bv : bh;
    float* outp = which ? g_v : g_h;

    gemm_tile_128<true, true>(
        x  + (size_t)mt * 128 * IN_DIM, IN_DIM,          // A[i,k], k-fast
        Wm + (size_t)nt * 128 * IN_DIM, IN_DIM,          // B[j,k], k-fast
        outp + (size_t)mt * 128 * BIAFF + nt * 128, BIAFF,
        IN_DIM, bb, nt * 128);
}

// ---------------------------------------------------------------------------
// K2 (phase A): T[b,h,l,d,y] = sum_x h[b,l,h,x] * W[h,d,x,y]
// per CTA: (b, h, d, l-tile) -> 128x128x128 GEMM (NN: B j-fast)
// grid = (256 = l2*128+d, 4 heads, 4 batch)
// ---------------------------------------------------------------------------
__global__ __launch_bounds__(256, 2)
void k_phaseA(const float* __restrict__ W)
{
    const int d  = blockIdx.x & 127;
    const int l2 = blockIdx.x >> 7;
    const int h  = blockIdx.y;
    const int b  = blockIdx.z;

    const float* A = g_h + ((size_t)(b * MAX_LEN + l2 * 128)) * BIAFF + h * HD; // [l,x], lda=512
    const float* B = W   + ((size_t)(h * HD + d)) * (HD * HD);                  // [x,y], ldb=128
    float*       C = g_T + ((size_t)((b * NHEAD + h) * MAX_LEN + l2 * 128)) * (HD * HD)
                         + (size_t)d * HD;                                      // [l, y], ldc=16384

    gemm_tile_128<false, false>(A, BIAFF, B, HD, C, HD * HD, HD, nullptr, 0);
}

// ---------------------------------------------------------------------------
// K3 (phase B): out[b,l,k,h*128+d] = sum_y v[b,k,h,y] * T[b,h,l,d,y]
// per CTA: (b, h, l, k-tile) -> C[k,d] = V[k,y] @ T_l[d,y]^T  (NT: B k-fast)
// grid = (512 = l*2+k2, 4 heads, 4 batch)
// ---------------------------------------------------------------------------
__global__ __launch_bounds__(256, 2)
void k_phaseB(float* __restrict__ out)
{
    const int k2 = blockIdx.x & 1;
    const int l  = blockIdx.x >> 1;
    const int h  = blockIdx.y;
    const int b  = blockIdx.z;

    const float* A = g_v + ((size_t)(b * MAX_LEN + k2 * 128)) * BIAFF + h * HD; // [k,y], lda=512
    const float* B = g_T + ((size_t)((b * NHEAD + h) * MAX_LEN + l)) * (HD * HD); // [d,y], ldb=128
    float*       C = out + ((size_t)((b * MAX_LEN + l) * MAX_LEN + k2 * 128)) * OUTC
                         + h * HD;                                              // [k, d], ldc=512

    gemm_tile_128<true, false>(A, BIAFF, B, HD, C, OUTC, HD, nullptr, 0);
}

// ---------------------------------------------------------------------------
extern "C" void kernel_launch(void* const* d_in, const int* in_sizes, int n_in,
                              void* d_out, int out_size)
{
    const float* x  = (const float*)d_in[0];
    const float* Wh = (const float*)d_in[1];
    const float* bh = (const float*)d_in[2];
    const float* Wv = (const float*)d_in[3];
    const float* bv = (const float*)d_in[4];
    const float* W  = (const float*)d_in[5];
    float* out = (float*)d_out;

    k_mlp   <<<dim3(4,   8, 2), 256>>>(x, Wh, bh, Wv, bv);
    k_phaseA<<<dim3(256, 4, 4), 256>>>(W);
    k_phaseB<<<dim3(512, 4, 4), 256>>>(out);
    (void)in_sizes; (void)n_in; (void)out_size;
}

// round 8
// speedup vs baseline: 1.7575x; 1.7575x over previous
#include <cuda_runtime.h>
#include <cuda_bf16.h>
#include <cstdint>

#define BSZ      4
#define MAX_LEN  256
#define IN_DIM   1024
#define BIAFF    512
#define OUTC     512
#define NHEAD    4
#define HD       128

using bf16 = __nv_bfloat16;

// ---------------- device scratch (no runtime allocation allowed) -----------
__device__ bf16 g_x_hi[BSZ * MAX_LEN * IN_DIM];     // 2 MB
__device__ bf16 g_x_lo[BSZ * MAX_LEN * IN_DIM];
__device__ bf16 g_Wm_hi[2 * BIAFF * IN_DIM];        // Wh then Wv
__device__ bf16 g_Wm_lo[2 * BIAFF * IN_DIM];
__device__ bf16 g_h_hi[BSZ * MAX_LEN * BIAFF];
__device__ bf16 g_h_lo[BSZ * MAX_LEN * BIAFF];
__device__ bf16 g_v_hi[BSZ * MAX_LEN * BIAFF];
__device__ bf16 g_v_lo[BSZ * MAX_LEN * BIAFF];
__device__ bf16 g_Wt_hi[NHEAD * HD * HD * HD];      // W transposed: [h][d][y][x]
__device__ bf16 g_Wt_lo[NHEAD * HD * HD * HD];
__device__ bf16 g_T_hi[(size_t)BSZ * NHEAD * MAX_LEN * HD * HD];  // 134 MB
__device__ bf16 g_T_lo[(size_t)BSZ * NHEAD * MAX_LEN * HD * HD];

// ---------------- helpers ---------------------------------------------------
__device__ __forceinline__ uint32_t pack2(bf16 a, bf16 b) {
    __nv_bfloat162 t;
    t.x = a; t.y = b;
    return *reinterpret_cast<uint32_t*>(&t);
}

__device__ __forceinline__ void split1(float x, bf16& hi, bf16& lo) {
    hi = __float2bfloat16_rn(x);
    lo = __float2bfloat16_rn(x - __bfloat162float(hi));
}

#define MMA_BF16(C, A, B)                                                     \
    asm volatile(                                                             \
        "mma.sync.aligned.m16n8k16.row.col.f32.bf16.bf16.f32 "                \
        "{%0,%1,%2,%3}, {%4,%5,%6,%7}, {%8,%9}, {%0,%1,%2,%3};"               \
        : "+f"((C)[0]), "+f"((C)[1]), "+f"((C)[2]), "+f"((C)[3])              \
        : "r"((A)[0]), "r"((A)[1]), "r"((A)[2]), "r"((A)[3]),                 \
          "r"((B)[0]), "r"((B)[1]))

// ---------------- prep: fp32 -> bf16 hi/lo splitter -------------------------
__global__ __launch_bounds__(256)
void k_split(const float* __restrict__ in, bf16* __restrict__ hi,
             bf16* __restrict__ lo, int n4)
{
    int i = blockIdx.x * blockDim.x + threadIdx.x;
    if (i >= n4) return;
    float4 v = reinterpret_cast<const float4*>(in)[i];
    bf16 h0, h1, h2, h3, l0, l1, l2, l3;
    split1(v.x, h0, l0); split1(v.y, h1, l1);
    split1(v.z, h2, l2); split1(v.w, h3, l3);
    reinterpret_cast<uint32_t*>(hi)[2 * i]     = pack2(h0, h1);
    reinterpret_cast<uint32_t*>(hi)[2 * i + 1] = pack2(h2, h3);
    reinterpret_cast<uint32_t*>(lo)[2 * i]     = pack2(l0, l1);
    reinterpret_cast<uint32_t*>(lo)[2 * i + 1] = pack2(l2, l3);
}

// ---------------- prep: W[h,d,x,y] -> Wt[h,d,y,x] (split) -------------------
__global__ __launch_bounds__(256)
void k_wt(const float* __restrict__ W)
{
    const int xh = blockIdx.x;   // 0..1 (x half)
    const int d  = blockIdx.y;   // 0..127
    const int h  = blockIdx.z;   // 0..3
    __shared__ float s[64][129];

    const float* src = W + (((size_t)(h * HD + d)) * HD + xh * 64) * HD;  // [x][y]
    const int tid = threadIdx.x;
#pragma unroll
    for (int t = 0; t < 8; t++) {
        int idx = tid + t * 256;          // 0..2047
        int xr  = idx >> 5;               // 0..63
        int y4  = (idx & 31) * 4;
        float4 v = *(const float4*)(src + (size_t)xr * HD + y4);
        s[xr][y4]     = v.x; s[xr][y4 + 1] = v.y;
        s[xr][y4 + 2] = v.z; s[xr][y4 + 3] = v.w;
    }
    __syncthreads();

    bf16* dh = g_Wt_hi + ((size_t)(h * HD + d)) * HD * HD + xh * 64;
    bf16* dl = g_Wt_lo + ((size_t)(h * HD + d)) * HD * HD + xh * 64;
    const int y  = tid >> 1;              // 0..127
    const int xo = (tid & 1) * 32;        // 0 or 32 within this half
#pragma unroll
    for (int j = 0; j < 16; j++) {
        float a = s[xo + 2 * j][y];
        float b = s[xo + 2 * j + 1][y];
        bf16 ah, al, bh, bl;
        split1(a, ah, al); split1(b, bh, bl);
        *reinterpret_cast<uint32_t*>(dh + (size_t)y * HD + xo + 2 * j) = pack2(ah, bh);
        *reinterpret_cast<uint32_t*>(dl + (size_t)y * HD + xo + 2 * j) = pack2(al, bl);
    }
}

// ---------------- core: 128x128 tile GEMM via bf16-split mma -----------------
// A[row m][k] k-fast (hi/lo), B[row n][k] k-fast (hi/lo), fp32 accumulate.
// EPI: 0 = fp32 store, 1 = split-bf16 store, 2 = bias+LeakyReLU + split store
template <int EPI>
__device__ __forceinline__ void mma_tile(
    const bf16* __restrict__ Ahi, const bf16* __restrict__ Alo, int lda,
    const bf16* __restrict__ Bhi, const bf16* __restrict__ Blo, int ldb,
    int K,
    float* __restrict__ Cf, bf16* __restrict__ Chi, bf16* __restrict__ Clo,
    int ldc, const float* __restrict__ bias, int j0)
{
    constexpr int KCP = 40;  // row pitch (bf16) -> conflict-free frag LDS
    __shared__ bf16 sAh[128][KCP], sAl[128][KCP];
    __shared__ bf16 sBh[128][KCP], sBl[128][KCP];

    const int tid  = threadIdx.x;
    const int lane = tid & 31;
    const int wid  = tid >> 5;
    const int wm   = wid >> 2;        // 0..1   (64-row slabs)
    const int wn   = wid & 3;         // 0..3   (32-col slabs)
    const int g    = lane >> 2;       // 0..7
    const int tg   = lane & 3;        // 0..3

    float acc[4][4][4];
#pragma unroll
    for (int a = 0; a < 4; a++)
#pragma unroll
        for (int b = 0; b < 4; b++)
#pragma unroll
            for (int c = 0; c < 4; c++) acc[a][b][c] = 0.0f;

    // staging indices: 2 threads per row, 16 bf16 (32B) each
    const int sr = tid >> 1;
    const int sc = (tid & 1) * 16;

    for (int k0 = 0; k0 < K; k0 += 32) {
        {
            const uint4 a0 = *(const uint4*)(Ahi + (size_t)sr * lda + k0 + sc);
            const uint4 a1 = *(const uint4*)(Ahi + (size_t)sr * lda + k0 + sc + 8);
            const uint4 a2 = *(const uint4*)(Alo + (size_t)sr * lda + k0 + sc);
            const uint4 a3 = *(const uint4*)(Alo + (size_t)sr * lda + k0 + sc + 8);
            const uint4 b0 = *(const uint4*)(Bhi + (size_t)sr * ldb + k0 + sc);
            const uint4 b1 = *(const uint4*)(Bhi + (size_t)sr * ldb + k0 + sc + 8);
            const uint4 b2 = *(const uint4*)(Blo + (size_t)sr * ldb + k0 + sc);
            const uint4 b3 = *(const uint4*)(Blo + (size_t)sr * ldb + k0 + sc + 8);
            // rows are 80B apart -> 8B stores
            *(uint2*)&sAh[sr][sc]      = make_uint2(a0.x, a0.y);
            *(uint2*)&sAh[sr][sc + 4]  = make_uint2(a0.z, a0.w);
            *(uint2*)&sAh[sr][sc + 8]  = make_uint2(a1.x, a1.y);
            *(uint2*)&sAh[sr][sc + 12] = make_uint2(a1.z, a1.w);
            *(uint2*)&sAl[sr][sc]      = make_uint2(a2.x, a2.y);
            *(uint2*)&sAl[sr][sc + 4]  = make_uint2(a2.z, a2.w);
            *(uint2*)&sAl[sr][sc + 8]  = make_uint2(a3.x, a3.y);
            *(uint2*)&sAl[sr][sc + 12] = make_uint2(a3.z, a3.w);
            *(uint2*)&sBh[sr][sc]      = make_uint2(b0.x, b0.y);
            *(uint2*)&sBh[sr][sc + 4]  = make_uint2(b0.z, b0.w);
            *(uint2*)&sBh[sr][sc + 8]  = make_uint2(b1.x, b1.y);
            *(uint2*)&sBh[sr][sc + 12] = make_uint2(b1.z, b1.w);
            *(uint2*)&sBl[sr][sc]      = make_uint2(b2.x, b2.y);
            *(uint2*)&sBl[sr][sc + 4]  = make_uint2(b2.z, b2.w);
            *(uint2*)&sBl[sr][sc + 8]  = make_uint2(b3.x, b3.y);
            *(uint2*)&sBl[sr][sc + 12] = make_uint2(b3.z, b3.w);
        }
        __syncthreads();

#pragma unroll
        for (int ks = 0; ks < 32; ks += 16) {
            uint32_t ah[4][4], al[4][4], bh[4][2], bl[4][2];
#pragma unroll
            for (int mt = 0; mt < 4; mt++) {
                const int r0 = wm * 64 + mt * 16;
                ah[mt][0] = *(const uint32_t*)&sAh[r0 + g][ks + 2 * tg];
                ah[mt][1] = *(const uint32_t*)&sAh[r0 + g + 8][ks + 2 * tg];
                ah[mt][2] = *(const uint32_t*)&sAh[r0 + g][ks + 2 * tg + 8];
                ah[mt][3] = *(const uint32_t*)&sAh[r0 + g + 8][ks + 2 * tg + 8];
                al[mt][0] = *(const uint32_t*)&sAl[r0 + g][ks + 2 * tg];
                al[mt][1] = *(const uint32_t*)&sAl[r0 + g + 8][ks + 2 * tg];
                al[mt][2] = *(const uint32_t*)&sAl[r0 + g][ks + 2 * tg + 8];
                al[mt][3] = *(const uint32_t*)&sAl[r0 + g + 8][ks + 2 * tg + 8];
            }
#pragma unroll
            for (int nt = 0; nt < 4; nt++) {
                const int n0 = wn * 32 + nt * 8;
                bh[nt][0] = *(const uint32_t*)&sBh[n0 + g][ks + 2 * tg];
                bh[nt][1] = *(const uint32_t*)&sBh[n0 + g][ks + 2 * tg + 8];
                bl[nt][0] = *(const uint32_t*)&sBl[n0 + g][ks + 2 * tg];
                bl[nt][1] = *(const uint32_t*)&sBl[n0 + g][ks + 2 * tg + 8];
            }
#pragma unroll
            for (int mt = 0; mt < 4; mt++)
#pragma unroll
                for (int nt = 0; nt < 4; nt++) {
                    MMA_BF16(acc[mt][nt], ah[mt], bh[nt]);
                    MMA_BF16(acc[mt][nt], ah[mt], bl[nt]);
                    MMA_BF16(acc[mt][nt], al[mt], bh[nt]);
                }
        }
        __syncthreads();
    }

    // -------- epilogue --------
#pragma unroll
    for (int mt = 0; mt < 4; mt++) {
        const int row0 = wm * 64 + mt * 16 + g;
        const int row1 = row0 + 8;
#pragma unroll
        for (int nt = 0; nt < 4; nt++) {
            const int col = wn * 32 + nt * 8 + 2 * tg;
            float c0 = acc[mt][nt][0], c1 = acc[mt][nt][1];
            float c2 = acc[mt][nt][2], c3 = acc[mt][nt][3];
            if (EPI == 2) {
                const float b0 = bias[j0 + col], b1 = bias[j0 + col + 1];
                c0 += b0; c1 += b1; c2 += b0; c3 += b1;
                c0 = (c0 > 0.f) ? c0 : 0.01f * c0;
                c1 = (c1 > 0.f) ? c1 : 0.01f * c1;
                c2 = (c2 > 0.f) ? c2 : 0.01f * c2;
                c3 = (c3 > 0.f) ? c3 : 0.01f * c3;
            }
            if (EPI == 0) {
                *(float2*)(Cf + (size_t)row0 * ldc + col) = make_float2(c0, c1);
                *(float2*)(Cf + (size_t)row1 * ldc + col) = make_float2(c2, c3);
            } else {
                bf16 h0, h1, h2, h3, l0, l1, l2, l3;
                split1(c0, h0, l0); split1(c1, h1, l1);
                split1(c2, h2, l2); split1(c3, h3, l3);
                *(uint32_t*)(Chi + (size_t)row0 * ldc + col) = pack2(h0, h1);
                *(uint32_t*)(Chi + (size_t)row1 * ldc + col) = pack2(h2, h3);
                *(uint32_t*)(Clo + (size_t)row0 * ldc + col) = pack2(l0, l1);
                *(uint32_t*)(Clo + (size_t)row1 * ldc + col) = pack2(l2, l3);
            }
        }
    }
}

// ---------------- K1: MLP h/v = LeakyReLU(x @ Wm^T + b), split-store --------
__global__ __launch_bounds__(256)
void k_mlp(const float* __restrict__ bh, const float* __restrict__ bv)
{
    const int nt = blockIdx.x;      // output-feature tile (4)
    const int mt = blockIdx.y;      // (b*l) tile (8)
    const int which = blockIdx.z;   // 0 -> h, 1 -> v

    const bf16* Ah = g_x_hi + (size_t)mt * 128 * IN_DIM;
    const bf16* Al = g_x_lo + (size_t)mt * 128 * IN_DIM;
    const bf16* Bh = g_Wm_hi + (size_t)which * BIAFF * IN_DIM + (size_t)nt * 128 * IN_DIM;
    const bf16* Bl = g_Wm_lo + (size_t)which * BIAFF * IN_DIM + (size_t)nt * 128 * IN_DIM;
    bf16* Oh = (which ? g_v_hi : g_h_hi) + (size_t)mt * 128 * BIAFF + nt * 128;
    bf16* Ol = (which ? g_v_lo : g_h_lo) + (size_t)mt * 128 * BIAFF + nt * 128;
    const float* bias = which ? bv : bh;

    mma_tile<2>(Ah, Al, IN_DIM, Bh, Bl, IN_DIM, IN_DIM,
                nullptr, Oh, Ol, BIAFF, bias, nt * 128);
}

// ---------------- K2: T[b,h,l,d,y] = sum_x h[b,l,h,x] * W[h,d,x,y] ----------
__global__ __launch_bounds__(256)
void k_phaseA()
{
    const int d  = blockIdx.x & 127;
    const int l2 = blockIdx.x >> 7;
    const int h  = blockIdx.y;
    const int b  = blockIdx.z;

    const size_t aoff = ((size_t)(b * MAX_LEN + l2 * 128)) * BIAFF + h * HD;
    const size_t boff = ((size_t)(h * HD + d)) * HD * HD;           // Wt[h][d][y][x]
    const size_t coff = (((size_t)(b * NHEAD + h) * MAX_LEN + l2 * 128)) * (HD * HD)
                        + (size_t)d * HD;

    mma_tile<1>(g_h_hi + aoff, g_h_lo + aoff, BIAFF,
                g_Wt_hi + boff, g_Wt_lo + boff, HD, HD,
                nullptr, g_T_hi + coff, g_T_lo + coff, HD * HD, nullptr, 0);
}

// ---------------- K3: out[b,l,k,h*128+d] = sum_y v[b,k,h,y] * T[b,h,l,d,y] --
__global__ __launch_bounds__(256)
void k_phaseB(float* __restrict__ out)
{
    const int k2 = blockIdx.x & 1;
    const int l  = blockIdx.x >> 1;
    const int h  = blockIdx.y;
    const int b  = blockIdx.z;

    const size_t aoff = ((size_t)(b * MAX_LEN + k2 * 128)) * BIAFF + h * HD;
    const size_t boff = (((size_t)(b * NHEAD + h) * MAX_LEN + l)) * (HD * HD);
    const size_t coff = (((size_t)(b * MAX_LEN + l) * MAX_LEN + k2 * 128)) * OUTC + h * HD;

    mma_tile<0>(g_v_hi + aoff, g_v_lo + aoff, BIAFF,
                g_T_hi + boff, g_T_lo + boff, HD, HD,
                out + coff, nullptr, nullptr, OUTC, nullptr, 0);
}

// ---------------------------------------------------------------------------
extern "C" void kernel_launch(void* const* d_in, const int* in_sizes, int n_in,
                              void* d_out, int out_size)
{
    const float* x  = (const float*)d_in[0];
    const float* Wh = (const float*)d_in[1];
    const float* bh = (const float*)d_in[2];
    const float* Wv = (const float*)d_in[3];
    const float* bv = (const float*)d_in[4];
    const float* W  = (const float*)d_in[5];
    float* out = (float*)d_out;

    bf16 *xh, *xl, *wmh, *wml;
    cudaGetSymbolAddress((void**)&xh,  g_x_hi);
    cudaGetSymbolAddress((void**)&xl,  g_x_lo);
    cudaGetSymbolAddress((void**)&wmh, g_Wm_hi);
    cudaGetSymbolAddress((void**)&wml, g_Wm_lo);

    // split x, Wh, Wv into bf16 hi/lo
    k_split<<<(BSZ * MAX_LEN * IN_DIM / 4 + 255) / 256, 256>>>(x, xh, xl,
            BSZ * MAX_LEN * IN_DIM / 4);
    k_split<<<(BIAFF * IN_DIM / 4 + 255) / 256, 256>>>(Wh, wmh, wml,
            BIAFF * IN_DIM / 4);
    k_split<<<(BIAFF * IN_DIM / 4 + 255) / 256, 256>>>(Wv,
            wmh + (size_t)BIAFF * IN_DIM, wml + (size_t)BIAFF * IN_DIM,
            BIAFF * IN_DIM / 4);
    // transpose + split W
    k_wt<<<dim3(2, 128, 4), 256>>>(W);

    k_mlp   <<<dim3(4,   8, 2), 256>>>(bh, bv);
    k_phaseA<<<dim3(256, 4, 4), 256>>>();
    k_phaseB<<<dim3(512, 4, 4), 256>>>(out);

    (void)in_sizes; (void)n_in; (void)out_size;
}

// round 12
// speedup vs baseline: 2.0266x; 1.1531x over previous
#include <cuda_runtime.h>
#include <cuda_bf16.h>
#include <cstdint>

#define BSZ      4
#define MAX_LEN  256
#define IN_DIM   1024
#define BIAFF    512
#define OUTC     512
#define NHEAD    4
#define HD       128

using bf16 = __nv_bfloat16;

// ---------------- device scratch ------------------------------------------
__device__ bf16 g_x_hi[BSZ * MAX_LEN * IN_DIM];
__device__ bf16 g_x_lo[BSZ * MAX_LEN * IN_DIM];
__device__ bf16 g_Wm_hi[2 * BIAFF * IN_DIM];        // Wh then Wv
__device__ bf16 g_Wm_lo[2 * BIAFF * IN_DIM];
__device__ bf16 g_h_hi[BSZ * MAX_LEN * BIAFF];
__device__ bf16 g_h_lo[BSZ * MAX_LEN * BIAFF];
__device__ bf16 g_v_hi[BSZ * MAX_LEN * BIAFF];
__device__ bf16 g_v_lo[BSZ * MAX_LEN * BIAFF];
__device__ bf16 g_Wt_hi[NHEAD * HD * HD * HD];      // W transposed: [h][d][y][x]
__device__ bf16 g_Wt_lo[NHEAD * HD * HD * HD];
__device__ bf16 g_T_hi[(size_t)BSZ * NHEAD * MAX_LEN * HD * HD];  // 134 MB
__device__ bf16 g_T_lo[(size_t)BSZ * NHEAD * MAX_LEN * HD * HD];

// ---------------- smem geometry --------------------------------------------
#define PITCH_B   80                       // bytes per smem row (40 bf16)
#define ARR_BYTES (128 * PITCH_B)          // 10240
#define STAGE_BYTES (4 * ARR_BYTES)        // 40960: Ah, Al, Bh, Bl
#define SM_BYTES (2 * STAGE_BYTES)         // 81920 (double buffer)

// ---------------- PTX helpers ----------------------------------------------
__device__ __forceinline__ uint32_t smem_u32(const void* p) {
    uint32_t a;
    asm("{ .reg .u64 t; cvta.to.shared.u64 t, %1; cvt.u32.u64 %0, t; }"
        : "=r"(a) : "l"(p));
    return a;
}

__device__ __forceinline__ void cp16(uint32_t dst, const void* src) {
    asm volatile("cp.async.cg.shared.global [%0], [%1], 16;"
                 :: "r"(dst), "l"(src) : "memory");
}
#define CP_COMMIT() asm volatile("cp.async.commit_group;" ::: "memory")
#define CP_WAIT1()  asm volatile("cp.async.wait_group 1;" ::: "memory")
#define CP_WAIT0()  asm volatile("cp.async.wait_group 0;" ::: "memory")

#define LDSM_X4(R, addr)                                                      \
    asm volatile("ldmatrix.sync.aligned.m8n8.x4.shared.b16 {%0,%1,%2,%3}, [%4];" \
                 : "=r"((R)[0]), "=r"((R)[1]), "=r"((R)[2]), "=r"((R)[3])     \
                 : "r"(addr))

#define MMA_BF16(C, A, B)                                                     \
    asm volatile(                                                             \
        "mma.sync.aligned.m16n8k16.row.col.f32.bf16.bf16.f32 "                \
        "{%0,%1,%2,%3}, {%4,%5,%6,%7}, {%8,%9}, {%0,%1,%2,%3};"               \
        : "+f"((C)[0]), "+f"((C)[1]), "+f"((C)[2]), "+f"((C)[3])              \
        : "r"((A)[0]), "r"((A)[1]), "r"((A)[2]), "r"((A)[3]),                 \
          "r"((B)[0]), "r"((B)[1]))

// ---------------- misc ------------------------------------------------------
__device__ __forceinline__ uint32_t pack2(bf16 a, bf16 b) {
    __nv_bfloat162 t; t.x = a; t.y = b;
    return *reinterpret_cast<uint32_t*>(&t);
}
__device__ __forceinline__ void split1(float x, bf16& hi, bf16& lo) {
    hi = __float2bfloat16_rn(x);
    lo = __float2bfloat16_rn(x - __bfloat162float(hi));
}

// ---------------- core: 128x128 tile GEMM, cp.async + ldmatrix + mma --------
// A[m][k] k-fast bf16 hi/lo; B[n][k] k-fast bf16 hi/lo; fp32 accum, 3 passes.
// EPI: 0 = fp32 store, 1 = split-bf16 store, 2 = bias + LeakyReLU + split store
template <int EPI>
__device__ __forceinline__ void run_tile(
    const bf16* __restrict__ Ahi, const bf16* __restrict__ Alo, int lda,
    const bf16* __restrict__ Bhi, const bf16* __restrict__ Blo, int ldb,
    int K,
    float* __restrict__ Cf, bf16* __restrict__ Chi, bf16* __restrict__ Clo,
    int ldc, const float* __restrict__ bias, int j0)
{
    extern __shared__ char smem[];
    const uint32_t sbase = smem_u32(smem);
    const int tid  = threadIdx.x;
    const int lane = tid & 31;
    const int wid  = tid >> 5;
    const int wm   = wid >> 2;        // 0..1  (64-row slab)
    const int wn   = wid & 3;         // 0..3  (32-col slab)
    const int g    = lane >> 2;       // 0..7
    const int tg   = lane & 3;        // 0..3

    float acc[4][4][4];
#pragma unroll
    for (int a = 0; a < 4; a++)
#pragma unroll
        for (int b = 0; b < 4; b++)
#pragma unroll
            for (int c = 0; c < 4; c++) acc[a][b][c] = 0.0f;

    // cp.async per-thread mapping: 64 rows/iter (tid>>2), 4 cols of 16B (tid&3)
    const int cr = tid >> 2;
    const int cc = tid & 3;

    const int nch = K >> 5;   // 32-k chunks

    auto load_chunk = [&](int k0, int stage) {
        const uint32_t sb = sbase + (uint32_t)stage * STAGE_BYTES;
#pragma unroll
        for (int it = 0; it < 2; it++) {
            const int r = cr + it * 64;
            const uint32_t doff = (uint32_t)r * PITCH_B + cc * 16;
            const size_t asrc = (size_t)r * lda + k0 + cc * 8;
            const size_t bsrc = (size_t)r * ldb + k0 + cc * 8;
            cp16(sb + 0 * ARR_BYTES + doff, Ahi + asrc);
            cp16(sb + 1 * ARR_BYTES + doff, Alo + asrc);
            cp16(sb + 2 * ARR_BYTES + doff, Bhi + bsrc);
            cp16(sb + 3 * ARR_BYTES + doff, Blo + bsrc);
        }
        CP_COMMIT();
    };

    load_chunk(0, 0);
    load_chunk(32, 1);

    // ldmatrix lane addressing: row = tile_row + (lane&15), col16 = (lane>>4)
    const int lr  = lane & 15;
    const int lc16 = (lane >> 4) * 16;

    for (int i = 0; i < nch; i++) {
        if (i + 2 < nch) CP_WAIT1(); else CP_WAIT0();
        __syncthreads();

        const uint32_t sb  = sbase + (uint32_t)(i & 1) * STAGE_BYTES;
        const uint32_t aAh = sb;
        const uint32_t aAl = sb + ARR_BYTES;
        const uint32_t aBh = sb + 2 * ARR_BYTES;
        const uint32_t aBl = sb + 3 * ARR_BYTES;

#pragma unroll
        for (int ks = 0; ks < 2; ks++) {
            const uint32_t colb = ks * 32 + lc16;

            // B fragments: 2 groups of 16 n-rows -> frags for 4 n-tiles
            uint32_t bh[8], bl[8];
#pragma unroll
            for (int np = 0; np < 2; np++) {
                const uint32_t rowb = (uint32_t)(wn * 32 + np * 16 + lr) * PITCH_B + colb;
                LDSM_X4(&bh[np * 4], aBh + rowb);
                LDSM_X4(&bl[np * 4], aBl + rowb);
            }

#pragma unroll
            for (int mt = 0; mt < 4; mt++) {
                const uint32_t rowb = (uint32_t)(wm * 64 + mt * 16 + lr) * PITCH_B + colb;
                uint32_t ah[4], al[4];
                LDSM_X4(ah, aAh + rowb);
                LDSM_X4(al, aAl + rowb);
#pragma unroll
                for (int nt = 0; nt < 4; nt++) {
                    uint32_t Bh2[2] = { bh[(nt >> 1) * 4 + (nt & 1)],
                                        bh[(nt >> 1) * 4 + 2 + (nt & 1)] };
                    uint32_t Bl2[2] = { bl[(nt >> 1) * 4 + (nt & 1)],
                                        bl[(nt >> 1) * 4 + 2 + (nt & 1)] };
                    MMA_BF16(acc[mt][nt], ah, Bh2);
                    MMA_BF16(acc[mt][nt], ah, Bl2);
                    MMA_BF16(acc[mt][nt], al, Bh2);
                }
            }
        }
        __syncthreads();
        if (i + 2 < nch) load_chunk((i + 2) * 32, i & 1);
    }

    // -------- epilogue --------
#pragma unroll
    for (int mt = 0; mt < 4; mt++) {
        const int row0 = wm * 64 + mt * 16 + g;
        const int row1 = row0 + 8;
#pragma unroll
        for (int nt = 0; nt < 4; nt++) {
            const int col = wn * 32 + nt * 8 + 2 * tg;
            float c0 = acc[mt][nt][0], c1 = acc[mt][nt][1];
            float c2 = acc[mt][nt][2], c3 = acc[mt][nt][3];
            if (EPI == 2) {
                const float b0 = bias[j0 + col], b1 = bias[j0 + col + 1];
                c0 += b0; c1 += b1; c2 += b0; c3 += b1;
                c0 = (c0 > 0.f) ? c0 : 0.01f * c0;
                c1 = (c1 > 0.f) ? c1 : 0.01f * c1;
                c2 = (c2 > 0.f) ? c2 : 0.01f * c2;
                c3 = (c3 > 0.f) ? c3 : 0.01f * c3;
            }
            if (EPI == 0) {
                *(float2*)(Cf + (size_t)row0 * ldc + col) = make_float2(c0, c1);
                *(float2*)(Cf + (size_t)row1 * ldc + col) = make_float2(c2, c3);
            } else {
                bf16 h0, h1, h2, h3, l0, l1, l2, l3;
                split1(c0, h0, l0); split1(c1, h1, l1);
                split1(c2, h2, l2); split1(c3, h3, l3);
                *(uint32_t*)(Chi + (size_t)row0 * ldc + col) = pack2(h0, h1);
                *(uint32_t*)(Chi + (size_t)row1 * ldc + col) = pack2(h2, h3);
                *(uint32_t*)(Clo + (size_t)row0 * ldc + col) = pack2(l0, l1);
                *(uint32_t*)(Clo + (size_t)row1 * ldc + col) = pack2(l2, l3);
            }
        }
    }
}

// ---------------- prep: fp32 -> bf16 hi/lo splitter -------------------------
__global__ __launch_bounds__(256)
void k_split(const float* __restrict__ in, bf16* __restrict__ hi,
             bf16* __restrict__ lo, int n4)
{
    int i = blockIdx.x * blockDim.x + threadIdx.x;
    if (i >= n4) return;
    float4 v = reinterpret_cast<const float4*>(in)[i];
    bf16 h0, h1, h2, h3, l0, l1, l2, l3;
    split1(v.x, h0, l0); split1(v.y, h1, l1);
    split1(v.z, h2, l2); split1(v.w, h3, l3);
    reinterpret_cast<uint32_t*>(hi)[2 * i]     = pack2(h0, h1);
    reinterpret_cast<uint32_t*>(hi)[2 * i + 1] = pack2(h2, h3);
    reinterpret_cast<uint32_t*>(lo)[2 * i]     = pack2(l0, l1);
    reinterpret_cast<uint32_t*>(lo)[2 * i + 1] = pack2(l2, l3);
}

// ---------------- prep: W[h,d,x,y] -> Wt[h,d,y,x] (split) -------------------
__global__ __launch_bounds__(256)
void k_wt(const float* __restrict__ W)
{
    const int xh = blockIdx.x, d = blockIdx.y, h = blockIdx.z;
    __shared__ float s[64][129];

    const float* src = W + (((size_t)(h * HD + d)) * HD + xh * 64) * HD;
    const int tid = threadIdx.x;
#pragma unroll
    for (int t = 0; t < 8; t++) {
        int idx = tid + t * 256;
        int xr = idx >> 5, y4 = (idx & 31) * 4;
        float4 v = *(const float4*)(src + (size_t)xr * HD + y4);
        s[xr][y4] = v.x; s[xr][y4 + 1] = v.y; s[xr][y4 + 2] = v.z; s[xr][y4 + 3] = v.w;
    }
    __syncthreads();

    bf16* dh = g_Wt_hi + ((size_t)(h * HD + d)) * HD * HD + xh * 64;
    bf16* dl = g_Wt_lo + ((size_t)(h * HD + d)) * HD * HD + xh * 64;
    const int y = tid >> 1, xo = (tid & 1) * 32;
#pragma unroll
    for (int j = 0; j < 16; j++) {
        float a = s[xo + 2 * j][y];
        float b = s[xo + 2 * j + 1][y];
        bf16 ah, al, bh2, bl2;
        split1(a, ah, al); split1(b, bh2, bl2);
        *(uint32_t*)(dh + (size_t)y * HD + xo + 2 * j) = pack2(ah, bh2);
        *(uint32_t*)(dl + (size_t)y * HD + xo + 2 * j) = pack2(al, bl2);
    }
}

// ---------------- K1: MLP ---------------------------------------------------
__global__ __launch_bounds__(256, 2)
void k_mlp(const float* __restrict__ bhv, const float* __restrict__ bvv)
{
    const int nt = blockIdx.x, mt = blockIdx.y, which = blockIdx.z;
    const bf16* Ah = g_x_hi + (size_t)mt * 128 * IN_DIM;
    const bf16* Al = g_x_lo + (size_t)mt * 128 * IN_DIM;
    const bf16* Bh = g_Wm_hi + (size_t)which * BIAFF * IN_DIM + (size_t)nt * 128 * IN_DIM;
    const bf16* Bl = g_Wm_lo + (size_t)which * BIAFF * IN_DIM + (size_t)nt * 128 * IN_DIM;
    bf16* Oh = (which ? g_v_hi : g_h_hi) + (size_t)mt * 128 * BIAFF + nt * 128;
    bf16* Ol = (which ? g_v_lo : g_h_lo) + (size_t)mt * 128 * BIAFF + nt * 128;
    const float* bias = which ? bvv : bhv;

    run_tile<2>(Ah, Al, IN_DIM, Bh, Bl, IN_DIM, IN_DIM,
                nullptr, Oh, Ol, BIAFF, bias, nt * 128);
}

// ---------------- K2: phase A  T[b,h,l,d,y] = sum_x h[b,l,h,x] W[h,d,x,y] ---
__global__ __launch_bounds__(256, 2)
void k_phaseA()
{
    const int d = blockIdx.x & 127, l2 = blockIdx.x >> 7;
    const int h = blockIdx.y, b = blockIdx.z;

    const size_t aoff = ((size_t)(b * MAX_LEN + l2 * 128)) * BIAFF + h * HD;
    const size_t boff = ((size_t)(h * HD + d)) * HD * HD;
    const size_t coff = (((size_t)(b * NHEAD + h) * MAX_LEN + l2 * 128)) * (HD * HD)
                        + (size_t)d * HD;

    run_tile<1>(g_h_hi + aoff, g_h_lo + aoff, BIAFF,
                g_Wt_hi + boff, g_Wt_lo + boff, HD, HD,
                nullptr, g_T_hi + coff, g_T_lo + coff, HD * HD, nullptr, 0);
}

// ---------------- K3: phase B  out[b,l,k,h*128+d] = sum_y v·T ---------------
__global__ __launch_bounds__(256, 2)
void k_phaseB(float* __restrict__ out)
{
    const int k2 = blockIdx.x & 1, l = blockIdx.x >> 1;
    const int h = blockIdx.y, b = blockIdx.z;

    const size_t aoff = ((size_t)(b * MAX_LEN + k2 * 128)) * BIAFF + h * HD;
    const size_t boff = (((size_t)(b * NHEAD + h) * MAX_LEN + l)) * (HD * HD);
    const size_t coff = (((size_t)(b * MAX_LEN + l) * MAX_LEN + k2 * 128)) * OUTC + h * HD;

    run_tile<0>(g_v_hi + aoff, g_v_lo + aoff, BIAFF,
                g_T_hi + boff, g_T_lo + boff, HD, HD,
                out + coff, nullptr, nullptr, OUTC, nullptr, 0);
}

// ---------------------------------------------------------------------------
extern "C" void kernel_launch(void* const* d_in, const int* in_sizes, int n_in,
                              void* d_out, int out_size)
{
    const float* x  = (const float*)d_in[0];
    const float* Wh = (const float*)d_in[1];
    const float* bh = (const float*)d_in[2];
    const float* Wv = (const float*)d_in[3];
    const float* bv = (const float*)d_in[4];
    const float* W  = (const float*)d_in[5];
    float* out = (float*)d_out;

    bf16 *xh, *xl, *wmh, *wml;
    cudaGetSymbolAddress((void**)&xh,  g_x_hi);
    cudaGetSymbolAddress((void**)&xl,  g_x_lo);
    cudaGetSymbolAddress((void**)&wmh, g_Wm_hi);
    cudaGetSymbolAddress((void**)&wml, g_Wm_lo);

    cudaFuncSetAttribute(k_mlp,    cudaFuncAttributeMaxDynamicSharedMemorySize, SM_BYTES);
    cudaFuncSetAttribute(k_phaseA, cudaFuncAttributeMaxDynamicSharedMemorySize, SM_BYTES);
    cudaFuncSetAttribute(k_phaseB, cudaFuncAttributeMaxDynamicSharedMemorySize, SM_BYTES);

    k_split<<<(BSZ * MAX_LEN * IN_DIM / 4 + 255) / 256, 256>>>(x, xh, xl,
            BSZ * MAX_LEN * IN_DIM / 4);
    k_split<<<(BIAFF * IN_DIM / 4 + 255) / 256, 256>>>(Wh, wmh, wml,
            BIAFF * IN_DIM / 4);
    k_split<<<(BIAFF * IN_DIM / 4 + 255) / 256, 256>>>(Wv,
            wmh + (size_t)BIAFF * IN_DIM, wml + (size_t)BIAFF * IN_DIM,
            BIAFF * IN_DIM / 4);
    k_wt<<<dim3(2, 128, 4), 256>>>(W);

    k_mlp   <<<dim3(4,   8, 2), 256, SM_BYTES>>>(bh, bv);
    k_phaseA<<<dim3(256, 4, 4), 256, SM_BYTES>>>();
    k_phaseB<<<dim3(512, 4, 4), 256, SM_BYTES>>>(out);

    (void)in_sizes; (void)n_in; (void)out_size;
}

// round 15
// speedup vs baseline: 2.0550x; 1.0140x over previous
#include <cuda_runtime.h>
#include <cuda_bf16.h>
#include <cstdint>

#define BSZ      4
#define MAX_LEN  256
#define IN_DIM   1024
#define BIAFF    512
#define OUTC     512
#define NHEAD    4
#define HD       128

using bf16 = __nv_bfloat16;

// ---------------- device scratch ------------------------------------------
__device__ bf16 g_x_hi[BSZ * MAX_LEN * IN_DIM];
__device__ bf16 g_x_lo[BSZ * MAX_LEN * IN_DIM];
__device__ bf16 g_Wm_hi[2 * BIAFF * IN_DIM];        // Wh then Wv
__device__ bf16 g_Wm_lo[2 * BIAFF * IN_DIM];
__device__ bf16 g_h_hi[BSZ * MAX_LEN * BIAFF];
__device__ bf16 g_h_lo[BSZ * MAX_LEN * BIAFF];
__device__ bf16 g_v_hi[BSZ * MAX_LEN * BIAFF];
__device__ bf16 g_v_lo[BSZ * MAX_LEN * BIAFF];
__device__ bf16 g_W_hi[NHEAD * HD * HD * HD];       // natural layout [h][d][x][y]
__device__ bf16 g_W_lo[NHEAD * HD * HD * HD];
__device__ bf16 g_T_hi[(size_t)BSZ * NHEAD * MAX_LEN * HD * HD];  // 134 MB
__device__ bf16 g_T_lo[(size_t)BSZ * NHEAD * MAX_LEN * HD * HD];

// ---------------- smem geometry --------------------------------------------
#define PITCH_B   80                       // bytes per smem row (40 bf16), k-fast tiles

// ---------------- PTX helpers ----------------------------------------------
__device__ __forceinline__ uint32_t smem_u32(const void* p) {
    uint32_t a;
    asm("{ .reg .u64 t; cvta.to.shared.u64 t, %1; cvt.u32.u64 %0, t; }"
        : "=r"(a) : "l"(p));
    return a;
}

__device__ __forceinline__ void cp16(uint32_t dst, const void* src) {
    asm volatile("cp.async.cg.shared.global [%0], [%1], 16;"
                 :: "r"(dst), "l"(src) : "memory");
}
#define CP_COMMIT() asm volatile("cp.async.commit_group;" ::: "memory")
#define CP_WAIT1()  asm volatile("cp.async.wait_group 1;" ::: "memory")
#define CP_WAIT0()  asm volatile("cp.async.wait_group 0;" ::: "memory")

#define LDSM_X4(R, addr)                                                      \
    asm volatile("ldmatrix.sync.aligned.m8n8.x4.shared.b16 {%0,%1,%2,%3}, [%4];" \
                 : "=r"((R)[0]), "=r"((R)[1]), "=r"((R)[2]), "=r"((R)[3])     \
                 : "r"(addr))

#define LDSM_X4_T(R, addr)                                                    \
    asm volatile("ldmatrix.sync.aligned.m8n8.x4.trans.shared.b16 {%0,%1,%2,%3}, [%4];" \
                 : "=r"((R)[0]), "=r"((R)[1]), "=r"((R)[2]), "=r"((R)[3])     \
                 : "r"(addr))

#define MMA_BF16(C, A, B)                                                     \
    asm volatile(                                                             \
        "mma.sync.aligned.m16n8k16.row.col.f32.bf16.bf16.f32 "                \
        "{%0,%1,%2,%3}, {%4,%5,%6,%7}, {%8,%9}, {%0,%1,%2,%3};"               \
        : "+f"((C)[0]), "+f"((C)[1]), "+f"((C)[2]), "+f"((C)[3])              \
        : "r"((A)[0]), "r"((A)[1]), "r"((A)[2]), "r"((A)[3]),                 \
          "r"((B)[0]), "r"((B)[1]))

// ---------------- misc ------------------------------------------------------
__device__ __forceinline__ uint32_t pack2(bf16 a, bf16 b) {
    __nv_bfloat162 t; t.x = a; t.y = b;
    return *reinterpret_cast<uint32_t*>(&t);
}
__device__ __forceinline__ void split1(float x, bf16& hi, bf16& lo) {
    hi = __float2bfloat16_rn(x);
    lo = __float2bfloat16_rn(x - __bfloat162float(hi));
}

// ---------------- core: MT*64 x 128 tile GEMM (k-fast A and B) --------------
// EPI: 0 = fp32 store, 1 = split-bf16 store, 2 = bias + LeakyReLU + split store
template <int EPI, int MT>
__device__ __forceinline__ void run_tile(
    const bf16* __restrict__ Ahi, const bf16* __restrict__ Alo, int lda,
    const bf16* __restrict__ Bhi, const bf16* __restrict__ Blo, int ldb,
    int K,
    float* __restrict__ Cf, bf16* __restrict__ Chi, bf16* __restrict__ Clo,
    int ldc, const float* __restrict__ bias, int j0)
{
    constexpr int THREADS = MT * 128;
    constexpr int M = MT * 64;
    constexpr uint32_t ARR_A = (uint32_t)M * PITCH_B;
    constexpr uint32_t ARR_BT = 128u * PITCH_B;
    constexpr uint32_t STAGE = 2 * ARR_A + 2 * ARR_BT;

    extern __shared__ char smem[];
    const uint32_t sbase = smem_u32(smem);
    const int tid  = threadIdx.x;
    const int lane = tid & 31;
    const int wid  = tid >> 5;
    const int wm   = wid >> 2;        // 0..MT-1  (64-row slab)
    const int wn   = wid & 3;         // 0..3     (32-col slab)
    const int g    = lane >> 2;
    const int tg   = lane & 3;

    float acc[4][4][4];
#pragma unroll
    for (int a = 0; a < 4; a++)
#pragma unroll
        for (int b = 0; b < 4; b++)
#pragma unroll
            for (int c = 0; c < 4; c++) acc[a][b][c] = 0.0f;

    const int cc = tid & 3;           // 16B column
    const int nch = K >> 5;

    auto load_chunk = [&](int k0, int stage) {
        const uint32_t sb = sbase + (uint32_t)stage * STAGE;
#pragma unroll
        for (int it = 0; it < 2; it++) {
            const int r = (tid >> 2) + it * (THREADS / 4);
            const uint32_t doff = (uint32_t)r * PITCH_B + cc * 16;
            const size_t asrc = (size_t)r * lda + k0 + cc * 8;
            cp16(sb + doff, Ahi + asrc);
            cp16(sb + ARR_A + doff, Alo + asrc);
        }
        if (MT == 2) {
#pragma unroll
            for (int it = 0; it < 2; it++) {
                const int r = (tid >> 2) + it * 64;
                const uint32_t doff = (uint32_t)r * PITCH_B + cc * 16;
                const size_t bsrc = (size_t)r * ldb + k0 + cc * 8;
                cp16(sb + 2 * ARR_A + doff, Bhi + bsrc);
                cp16(sb + 2 * ARR_A + ARR_BT + doff, Blo + bsrc);
            }
        } else {
            const int r = tid >> 2;   // 0..127
            const uint32_t doff = (uint32_t)r * PITCH_B + cc * 16;
            const size_t bsrc = (size_t)r * ldb + k0 + cc * 8;
            cp16(sb + 2 * ARR_A + doff, Bhi + bsrc);
            cp16(sb + 2 * ARR_A + ARR_BT + doff, Blo + bsrc);
        }
        CP_COMMIT();
    };

    load_chunk(0, 0);
    load_chunk(32, 1);

    const int lr   = lane & 15;
    const int lc16 = (lane >> 4) * 16;

    for (int i = 0; i < nch; i++) {
        if (i + 2 < nch) CP_WAIT1(); else CP_WAIT0();
        __syncthreads();

        const uint32_t sb  = sbase + (uint32_t)(i & 1) * STAGE;
        const uint32_t aAh = sb;
        const uint32_t aAl = sb + ARR_A;
        const uint32_t aBh = sb + 2 * ARR_A;
        const uint32_t aBl = sb + 2 * ARR_A + ARR_BT;

#pragma unroll
        for (int ks = 0; ks < 2; ks++) {
            const uint32_t colb = ks * 32 + lc16;

            uint32_t bh[8], bl[8];
#pragma unroll
            for (int np = 0; np < 2; np++) {
                const uint32_t rowb = (uint32_t)(wn * 32 + np * 16 + lr) * PITCH_B + colb;
                LDSM_X4(&bh[np * 4], aBh + rowb);
                LDSM_X4(&bl[np * 4], aBl + rowb);
            }

#pragma unroll
            for (int mt = 0; mt < 4; mt++) {
                const uint32_t rowb = (uint32_t)(wm * 64 + mt * 16 + lr) * PITCH_B + colb;
                uint32_t ah[4], al[4];
                LDSM_X4(ah, aAh + rowb);
                LDSM_X4(al, aAl + rowb);
#pragma unroll
                for (int nt = 0; nt < 4; nt++) {
                    uint32_t Bh2[2] = { bh[(nt >> 1) * 4 + (nt & 1)],
                                        bh[(nt >> 1) * 4 + 2 + (nt & 1)] };
                    uint32_t Bl2[2] = { bl[(nt >> 1) * 4 + (nt & 1)],
                                        bl[(nt >> 1) * 4 + 2 + (nt & 1)] };
                    MMA_BF16(acc[mt][nt], ah, Bh2);
                    MMA_BF16(acc[mt][nt], ah, Bl2);
                    MMA_BF16(acc[mt][nt], al, Bh2);
                }
            }
        }
        __syncthreads();
        if (i + 2 < nch) load_chunk((i + 2) * 32, i & 1);
    }

    // -------- epilogue --------
#pragma unroll
    for (int mt = 0; mt < 4; mt++) {
        const int row0 = wm * 64 + mt * 16 + g;
        const int row1 = row0 + 8;
#pragma unroll
        for (int nt = 0; nt < 4; nt++) {
            const int col = wn * 32 + nt * 8 + 2 * tg;
            float c0 = acc[mt][nt][0], c1 = acc[mt][nt][1];
            float c2 = acc[mt][nt][2], c3 = acc[mt][nt][3];
            if (EPI == 2) {
                const float b0 = bias[j0 + col], b1 = bias[j0 + col + 1];
                c0 += b0; c1 += b1; c2 += b0; c3 += b1;
                c0 = (c0 > 0.f) ? c0 : 0.01f * c0;
                c1 = (c1 > 0.f) ? c1 : 0.01f * c1;
                c2 = (c2 > 0.f) ? c2 : 0.01f * c2;
                c3 = (c3 > 0.f) ? c3 : 0.01f * c3;
            }
            if (EPI == 0) {
                *(float2*)(Cf + (size_t)row0 * ldc + col) = make_float2(c0, c1);
                *(float2*)(Cf + (size_t)row1 * ldc + col) = make_float2(c2, c3);
            } else {
                bf16 h0, h1, h2, h3, l0, l1, l2, l3;
                split1(c0, h0, l0); split1(c1, h1, l1);
                split1(c2, h2, l2); split1(c3, h3, l3);
                *(uint32_t*)(Chi + (size_t)row0 * ldc + col) = pack2(h0, h1);
                *(uint32_t*)(Chi + (size_t)row1 * ldc + col) = pack2(h2, h3);
                *(uint32_t*)(Clo + (size_t)row0 * ldc + col) = pack2(l0, l1);
                *(uint32_t*)(Clo + (size_t)row1 * ldc + col) = pack2(l2, l3);
            }
        }
    }
}

// ---------------- prep: fp32 -> bf16 hi/lo splitter -------------------------
__global__ __launch_bounds__(256)
void k_split(const float* __restrict__ in, bf16* __restrict__ hi,
             bf16* __restrict__ lo, int n4)
{
    int i = blockIdx.x * blockDim.x + threadIdx.x;
    if (i >= n4) return;
    float4 v = reinterpret_cast<const float4*>(in)[i];
    bf16 h0, h1, h2, h3, l0, l1, l2, l3;
    split1(v.x, h0, l0); split1(v.y, h1, l1);
    split1(v.z, h2, l2); split1(v.w, h3, l3);
    reinterpret_cast<uint32_t*>(hi)[2 * i]     = pack2(h0, h1);
    reinterpret_cast<uint32_t*>(hi)[2 * i + 1] = pack2(h2, h3);
    reinterpret_cast<uint32_t*>(lo)[2 * i]     = pack2(l0, l1);
    reinterpret_cast<uint32_t*>(lo)[2 * i + 1] = pack2(l2, l3);
}

// ---------------- K1: MLP ---------------------------------------------------
__global__ __launch_bounds__(256, 2)
void k_mlp(const float* __restrict__ bhv, const float* __restrict__ bvv)
{
    const int nt = blockIdx.x, mt = blockIdx.y, which = blockIdx.z;
    const bf16* Ah = g_x_hi + (size_t)mt * 128 * IN_DIM;
    const bf16* Al = g_x_lo + (size_t)mt * 128 * IN_DIM;
    const bf16* Bh = g_Wm_hi + (size_t)which * BIAFF * IN_DIM + (size_t)nt * 128 * IN_DIM;
    const bf16* Bl = g_Wm_lo + (size_t)which * BIAFF * IN_DIM + (size_t)nt * 128 * IN_DIM;
    bf16* Oh = (which ? g_v_hi : g_h_hi) + (size_t)mt * 128 * BIAFF + nt * 128;
    bf16* Ol = (which ? g_v_lo : g_h_lo) + (size_t)mt * 128 * BIAFF + nt * 128;
    const float* bias = which ? bvv : bhv;

    run_tile<2, 2>(Ah, Al, IN_DIM, Bh, Bl, IN_DIM, IN_DIM,
                   nullptr, Oh, Ol, BIAFF, bias, nt * 128);
}

// ---------------- K2: phase A (trans-B from natural W layout) ---------------
// GEMM per CTA: M=l(128), N=y(128), K=x(128).
// A = h tile (k-fast, pitch 80). B = W[h,d] chunk: 32 x-rows of 128 y bf16,
// pitch 272 B (conflict-free for ldmatrix.trans), frags via ldmatrix.x4.trans.
#define PA_PITCH 272
#define PA_ARR_A (128u * PITCH_B)          // 10240
#define PA_ARR_B (32u * PA_PITCH)          // 8704
#define PA_STAGE (2 * PA_ARR_A + 2 * PA_ARR_B)   // 37888
#define PA_SMEM  (2 * PA_STAGE)            // 75776

__global__ __launch_bounds__(256, 2)
void k_phaseA()
{
    const int b  = blockIdx.x >> 1;
    const int l2 = blockIdx.x & 1;
    const int d  = blockIdx.y;
    const int h  = blockIdx.z;

    const bf16* Ahi = g_h_hi + ((size_t)(b * MAX_LEN + l2 * 128)) * BIAFF + h * HD;
    const bf16* Alo = g_h_lo + ((size_t)(b * MAX_LEN + l2 * 128)) * BIAFF + h * HD;
    const bf16* Bhi = g_W_hi + ((size_t)(h * HD + d)) * HD * HD;   // [x][y]
    const bf16* Blo = g_W_lo + ((size_t)(h * HD + d)) * HD * HD;
    bf16* Chi = g_T_hi + (((size_t)(b * NHEAD + h) * MAX_LEN + l2 * 128)) * (HD * HD)
                       + (size_t)d * HD;
    bf16* Clo = g_T_lo + (((size_t)(b * NHEAD + h) * MAX_LEN + l2 * 128)) * (HD * HD)
                       + (size_t)d * HD;
    const int ldc = HD * HD;

    extern __shared__ char smem[];
    const uint32_t sbase = smem_u32(smem);
    const int tid  = threadIdx.x;
    const int lane = tid & 31;
    const int wid  = tid >> 5;
    const int wm   = wid >> 2;
    const int wn   = wid & 3;
    const int g    = lane >> 2;
    const int tg   = lane & 3;

    float acc[4][4][4];
#pragma unroll
    for (int a = 0; a < 4; a++)
#pragma unroll
        for (int bb = 0; bb < 4; bb++)
#pragma unroll
            for (int c = 0; c < 4; c++) acc[a][bb][c] = 0.0f;

    const int cc = tid & 3;

    auto load_chunk = [&](int k0, int stage) {
        const uint32_t sb = sbase + (uint32_t)stage * PA_STAGE;
        // A: 128 rows x 32 k, pitch 80
#pragma unroll
        for (int it = 0; it < 2; it++) {
            const int r = (tid >> 2) + it * 64;
            const uint32_t doff = (uint32_t)r * PITCH_B + cc * 16;
            const size_t asrc = (size_t)r * BIAFF + k0 + cc * 8;
            cp16(sb + doff, Ahi + asrc);
            cp16(sb + PA_ARR_A + doff, Alo + asrc);
        }
        // B: 32 x-rows x 128 y (256 B payload per row), pitch 272
#pragma unroll
        for (int it = 0; it < 2; it++) {
            const int o = tid + it * 256;       // 0..511
            const int r = o >> 4;               // x row 0..31
            const int c16 = o & 15;             // 16B col
            const uint32_t doff = (uint32_t)r * PA_PITCH + c16 * 16;
            const size_t bsrc = (size_t)(k0 + r) * HD + c16 * 8;
            cp16(sb + 2 * PA_ARR_A + doff, Bhi + bsrc);
            cp16(sb + 2 * PA_ARR_A + PA_ARR_B + doff, Blo + bsrc);
        }
        CP_COMMIT();
    };

    load_chunk(0, 0);
    load_chunk(32, 1);

    const int lr   = lane & 15;
    const int lc16 = (lane >> 4) * 16;

    for (int i = 0; i < 4; i++) {
        if (i + 2 < 4) CP_WAIT1(); else CP_WAIT0();
        __syncthreads();

        const uint32_t sb  = sbase + (uint32_t)(i & 1) * PA_STAGE;
        const uint32_t aAh = sb;
        const uint32_t aAl = sb + PA_ARR_A;
        const uint32_t aBh = sb + 2 * PA_ARR_A;
        const uint32_t aBl = sb + 2 * PA_ARR_A + PA_ARR_B;

#pragma unroll
        for (int ks = 0; ks < 2; ks++) {
            // B frags via trans ldmatrix: rows = x (k), cols = y (n)
            uint32_t bh[8], bl[8];
#pragma unroll
            for (int half = 0; half < 2; half++) {
                const uint32_t addr = (uint32_t)(ks * 16 + lr) * PA_PITCH
                                    + (uint32_t)(wn * 32 + half * 16 + (lane >> 4) * 8) * 2;
                LDSM_X4_T(&bh[half * 4], aBh + addr);
                LDSM_X4_T(&bl[half * 4], aBl + addr);
            }
            // bh[nt*2], bh[nt*2+1] = b0,b1 for n8-subtile nt (nt = 0..3)

#pragma unroll
            for (int mt = 0; mt < 4; mt++) {
                const uint32_t rowb = (uint32_t)(wm * 64 + mt * 16 + lr) * PITCH_B
                                    + ks * 32 + lc16;
                uint32_t ah[4], al[4];
                LDSM_X4(ah, aAh + rowb);
                LDSM_X4(al, aAl + rowb);
#pragma unroll
                for (int nt = 0; nt < 4; nt++) {
                    uint32_t Bh2[2] = { bh[nt * 2], bh[nt * 2 + 1] };
                    uint32_t Bl2[2] = { bl[nt * 2], bl[nt * 2 + 1] };
                    MMA_BF16(acc[mt][nt], ah, Bh2);
                    MMA_BF16(acc[mt][nt], ah, Bl2);
                    MMA_BF16(acc[mt][nt], al, Bh2);
                }
            }
        }
        __syncthreads();
        if (i + 2 < 4) load_chunk((i + 2) * 32, i & 1);
    }

    // epilogue: split-bf16 store to T
#pragma unroll
    for (int mt = 0; mt < 4; mt++) {
        const int row0 = wm * 64 + mt * 16 + g;
        const int row1 = row0 + 8;
#pragma unroll
        for (int nt = 0; nt < 4; nt++) {
            const int col = wn * 32 + nt * 8 + 2 * tg;
            bf16 h0, h1, h2, h3, l0, l1, l2, l3;
            split1(acc[mt][nt][0], h0, l0); split1(acc[mt][nt][1], h1, l1);
            split1(acc[mt][nt][2], h2, l2); split1(acc[mt][nt][3], h3, l3);
            *(uint32_t*)(Chi + (size_t)row0 * ldc + col) = pack2(h0, h1);
            *(uint32_t*)(Chi + (size_t)row1 * ldc + col) = pack2(h2, h3);
            *(uint32_t*)(Clo + (size_t)row0 * ldc + col) = pack2(l0, l1);
            *(uint32_t*)(Clo + (size_t)row1 * ldc + col) = pack2(l2, l3);
        }
    }
}

// ---------------- K3: phase B (M=256 merged, 512 threads) -------------------
__global__ __launch_bounds__(512, 1)
void k_phaseB(float* __restrict__ out)
{
    const int l = blockIdx.x;
    const int h = blockIdx.y, b = blockIdx.z;

    const size_t aoff = (size_t)(b * MAX_LEN) * BIAFF + h * HD;        // all 256 k rows
    const size_t boff = (((size_t)(b * NHEAD + h) * MAX_LEN + l)) * (HD * HD);
    const size_t coff = (((size_t)(b * MAX_LEN + l) * MAX_LEN)) * OUTC + h * HD;

    run_tile<0, 4>(g_v_hi + aoff, g_v_lo + aoff, BIAFF,
                   g_T_hi + boff, g_T_lo + boff, HD, HD,
                   out + coff, nullptr, nullptr, OUTC, nullptr, 0);
}

// ---------------- smem sizes ------------------------------------------------
#define SM_MT2 (2 * (2 * (128 * PITCH_B) + 2 * (128 * PITCH_B)))   // 81920
#define SM_MT4 (2 * (2 * (256 * PITCH_B) + 2 * (128 * PITCH_B)))   // 122880

// ---------------------------------------------------------------------------
extern "C" void kernel_launch(void* const* d_in, const int* in_sizes, int n_in,
                              void* d_out, int out_size)
{
    const float* x  = (const float*)d_in[0];
    const float* Wh = (const float*)d_in[1];
    const float* bh = (const float*)d_in[2];
    const float* Wv = (const float*)d_in[3];
    const float* bv = (const float*)d_in[4];
    const float* W  = (const float*)d_in[5];
    float* out = (float*)d_out;

    bf16 *xh, *xl, *wmh, *wml, *wh, *wl;
    cudaGetSymbolAddress((void**)&xh,  g_x_hi);
    cudaGetSymbolAddress((void**)&xl,  g_x_lo);
    cudaGetSymbolAddress((void**)&wmh, g_Wm_hi);
    cudaGetSymbolAddress((void**)&wml, g_Wm_lo);
    cudaGetSymbolAddress((void**)&wh,  g_W_hi);
    cudaGetSymbolAddress((void**)&wl,  g_W_lo);

    cudaFuncSetAttribute(k_mlp,    cudaFuncAttributeMaxDynamicSharedMemorySize, SM_MT2);
    cudaFuncSetAttribute(k_phaseA, cudaFuncAttributeMaxDynamicSharedMemorySize, PA_SMEM);
    cudaFuncSetAttribute(k_phaseB, cudaFuncAttributeMaxDynamicSharedMemorySize, SM_MT4);

    k_split<<<(BSZ * MAX_LEN * IN_DIM / 4 + 255) / 256, 256>>>(x, xh, xl,
            BSZ * MAX_LEN * IN_DIM / 4);
    k_split<<<(BIAFF * IN_DIM / 4 + 255) / 256, 256>>>(Wh, wmh, wml,
            BIAFF * IN_DIM / 4);
    k_split<<<(BIAFF * IN_DIM / 4 + 255) / 256, 256>>>(Wv,
            wmh + (size_t)BIAFF * IN_DIM, wml + (size_t)BIAFF * IN_DIM,
            BIAFF * IN_DIM / 4);
    k_split<<<(NHEAD * HD * HD * HD / 4 + 255) / 256, 256>>>(W, wh, wl,
            NHEAD * HD * HD * HD / 4);

    k_mlp   <<<dim3(4,   8, 2), 256, SM_MT2>>>(bh, bv);
    k_phaseA<<<dim3(8, 128, 4), 256, PA_SMEM>>>();
    k_phaseB<<<dim3(256, 4, 4), 512, SM_MT4>>>(out);

    (void)in_sizes; (void)n_in; (void)out_size;
}

// round 16
// speedup vs baseline: 2.4262x; 1.1806x over previous
#include <cuda_runtime.h>
#include <cuda_bf16.h>
#include <cstdint>

#define BSZ      4
#define MAX_LEN  256
#define IN_DIM   1024
#define BIAFF    512
#define OUTC     512
#define NHEAD    4
#define HD       128

using bf16 = __nv_bfloat16;

// ---------------- device scratch ------------------------------------------
__device__ bf16 g_x_hi[BSZ * MAX_LEN * IN_DIM];
__device__ bf16 g_x_lo[BSZ * MAX_LEN * IN_DIM];
__device__ bf16 g_Wm_hi[2 * BIAFF * IN_DIM];        // Wh then Wv
__device__ bf16 g_Wm_lo[2 * BIAFF * IN_DIM];
__device__ bf16 g_h_hi[BSZ * MAX_LEN * BIAFF];
__device__ bf16 g_h_lo[BSZ * MAX_LEN * BIAFF];
__device__ bf16 g_v_hi[BSZ * MAX_LEN * BIAFF];
__device__ bf16 g_v_lo[BSZ * MAX_LEN * BIAFF];
__device__ bf16 g_W_hi[NHEAD * HD * HD * HD];       // natural [h][d][x][y]
__device__ bf16 g_W_lo[NHEAD * HD * HD * HD];
__device__ bf16 g_T_hi[(size_t)BSZ * NHEAD * MAX_LEN * HD * HD];
__device__ bf16 g_T_lo[(size_t)BSZ * NHEAD * MAX_LEN * HD * HD];

// ---------------- PTX helpers ----------------------------------------------
__device__ __forceinline__ uint32_t smem_u32(const void* p) {
    uint32_t a;
    asm("{ .reg .u64 t; cvta.to.shared.u64 t, %1; cvt.u32.u64 %0, t; }"
        : "=r"(a) : "l"(p));
    return a;
}
__device__ __forceinline__ void cp16(uint32_t dst, const void* src) {
    asm volatile("cp.async.cg.shared.global [%0], [%1], 16;"
                 :: "r"(dst), "l"(src) : "memory");
}
#define CP_COMMIT() asm volatile("cp.async.commit_group;" ::: "memory")
#define CP_WAIT1()  asm volatile("cp.async.wait_group 1;" ::: "memory")
#define CP_WAIT0()  asm volatile("cp.async.wait_group 0;" ::: "memory")

#define LDSM_X4(R, addr)                                                      \
    asm volatile("ldmatrix.sync.aligned.m8n8.x4.shared.b16 {%0,%1,%2,%3}, [%4];" \
                 : "=r"((R)[0]), "=r"((R)[1]), "=r"((R)[2]), "=r"((R)[3])     \
                 : "r"(addr))
#define LDSM_X4_T(R, addr)                                                    \
    asm volatile("ldmatrix.sync.aligned.m8n8.x4.trans.shared.b16 {%0,%1,%2,%3}, [%4];" \
                 : "=r"((R)[0]), "=r"((R)[1]), "=r"((R)[2]), "=r"((R)[3])     \
                 : "r"(addr))
#define MMA_BF16(C, A, B)                                                     \
    asm volatile(                                                             \
        "mma.sync.aligned.m16n8k16.row.col.f32.bf16.bf16.f32 "                \
        "{%0,%1,%2,%3}, {%4,%5,%6,%7}, {%8,%9}, {%0,%1,%2,%3};"               \
        : "+f"((C)[0]), "+f"((C)[1]), "+f"((C)[2]), "+f"((C)[3])              \
        : "r"((A)[0]), "r"((A)[1]), "r"((A)[2]), "r"((A)[3]),                 \
          "r"((B)[0]), "r"((B)[1]))

__device__ __forceinline__ uint32_t pack2(bf16 a, bf16 b) {
    __nv_bfloat162 t; t.x = a; t.y = b;
    return *reinterpret_cast<uint32_t*>(&t);
}
__device__ __forceinline__ void split1(float x, bf16& hi, bf16& lo) {
    hi = __float2bfloat16_rn(x);
    lo = __float2bfloat16_rn(x - __bfloat162float(hi));
}
__device__ __forceinline__ void split_f4(const float* __restrict__ in,
                                         bf16* __restrict__ hi,
                                         bf16* __restrict__ lo, int i)
{
    float4 v = reinterpret_cast<const float4*>(in)[i];
    bf16 h0, h1, h2, h3, l0, l1, l2, l3;
    split1(v.x, h0, l0); split1(v.y, h1, l1);
    split1(v.z, h2, l2); split1(v.w, h3, l3);
    reinterpret_cast<uint32_t*>(hi)[2 * i]     = pack2(h0, h1);
    reinterpret_cast<uint32_t*>(hi)[2 * i + 1] = pack2(h2, h3);
    reinterpret_cast<uint32_t*>(lo)[2 * i]     = pack2(l0, l1);
    reinterpret_cast<uint32_t*>(lo)[2 * i + 1] = pack2(l2, l3);
}

// ---------------- prep: ONE kernel for all splits ---------------------------
__global__ __launch_bounds__(256)
void k_prep(const float* __restrict__ x, const float* __restrict__ Wh,
            const float* __restrict__ Wv, const float* __restrict__ W)
{
    const int blk = blockIdx.x, tid = threadIdx.x;
    if (blk < 1024) {                       // x: 262144 f4
        split_f4(x, g_x_hi, g_x_lo, blk * 256 + tid);
    } else if (blk < 1536) {                // Wh: 131072 f4
        split_f4(Wh, g_Wm_hi, g_Wm_lo, (blk - 1024) * 256 + tid);
    } else if (blk < 2048) {                // Wv
        split_f4(Wv, g_Wm_hi + (size_t)BIAFF * IN_DIM,
                 g_Wm_lo + (size_t)BIAFF * IN_DIM, (blk - 1536) * 256 + tid);
    } else {                                // W: 2097152 f4, 4 per thread
        int base = (blk - 2048) * 256 + tid;
#pragma unroll
        for (int j = 0; j < 4; j++)
            split_f4(W, g_W_hi, g_W_lo, base + j * 524288);
    }
}

// ---------------- generic tile GEMM (used by MLP only) ----------------------
#define PITCH_B 80
template <int EPI>
__device__ __forceinline__ void run_tile(
    const bf16* __restrict__ Ahi, const bf16* __restrict__ Alo, int lda,
    const bf16* __restrict__ Bhi, const bf16* __restrict__ Blo, int ldb,
    int K,
    bf16* __restrict__ Chi, bf16* __restrict__ Clo,
    int ldc, const float* __restrict__ bias, int j0)
{
    constexpr uint32_t ARR = 128u * PITCH_B;
    constexpr uint32_t STAGE = 4 * ARR;

    extern __shared__ char smem[];
    const uint32_t sbase = smem_u32(smem);
    const int tid  = threadIdx.x;
    const int lane = tid & 31;
    const int wid  = tid >> 5;
    const int wm   = wid >> 2;
    const int wn   = wid & 3;
    const int g    = lane >> 2;
    const int tg   = lane & 3;

    float acc[4][4][4];
#pragma unroll
    for (int a = 0; a < 4; a++)
#pragma unroll
        for (int b = 0; b < 4; b++)
#pragma unroll
            for (int c = 0; c < 4; c++) acc[a][b][c] = 0.0f;

    const int cc = tid & 3;
    const int nch = K >> 5;

    auto load_chunk = [&](int k0, int stage) {
        const uint32_t sb = sbase + (uint32_t)stage * STAGE;
#pragma unroll
        for (int it = 0; it < 2; it++) {
            const int r = (tid >> 2) + it * 64;
            const uint32_t doff = (uint32_t)r * PITCH_B + cc * 16;
            const size_t asrc = (size_t)r * lda + k0 + cc * 8;
            const size_t bsrc = (size_t)r * ldb + k0 + cc * 8;
            cp16(sb + doff, Ahi + asrc);
            cp16(sb + ARR + doff, Alo + asrc);
            cp16(sb + 2 * ARR + doff, Bhi + bsrc);
            cp16(sb + 3 * ARR + doff, Blo + bsrc);
        }
        CP_COMMIT();
    };

    load_chunk(0, 0);
    load_chunk(32, 1);

    const int lr   = lane & 15;
    const int lc16 = (lane >> 4) * 16;

    for (int i = 0; i < nch; i++) {
        if (i + 2 < nch) CP_WAIT1(); else CP_WAIT0();
        __syncthreads();

        const uint32_t sb  = sbase + (uint32_t)(i & 1) * STAGE;
#pragma unroll
        for (int ks = 0; ks < 2; ks++) {
            const uint32_t colb = ks * 32 + lc16;
            uint32_t bh[8], bl[8];
#pragma unroll
            for (int np = 0; np < 2; np++) {
                const uint32_t rowb = (uint32_t)(wn * 32 + np * 16 + lr) * PITCH_B + colb;
                LDSM_X4(&bh[np * 4], sb + 2 * ARR + rowb);
                LDSM_X4(&bl[np * 4], sb + 3 * ARR + rowb);
            }
#pragma unroll
            for (int mt = 0; mt < 4; mt++) {
                const uint32_t rowb = (uint32_t)(wm * 64 + mt * 16 + lr) * PITCH_B + colb;
                uint32_t ah[4], al[4];
                LDSM_X4(ah, sb + rowb);
                LDSM_X4(al, sb + ARR + rowb);
#pragma unroll
                for (int nt = 0; nt < 4; nt++) {
                    uint32_t Bh2[2] = { bh[(nt >> 1) * 4 + (nt & 1)],
                                        bh[(nt >> 1) * 4 + 2 + (nt & 1)] };
                    uint32_t Bl2[2] = { bl[(nt >> 1) * 4 + (nt & 1)],
                                        bl[(nt >> 1) * 4 + 2 + (nt & 1)] };
                    MMA_BF16(acc[mt][nt], ah, Bh2);
                    MMA_BF16(acc[mt][nt], ah, Bl2);
                    MMA_BF16(acc[mt][nt], al, Bh2);
                }
            }
        }
        __syncthreads();
        if (i + 2 < nch) load_chunk((i + 2) * 32, i & 1);
    }

#pragma unroll
    for (int mt = 0; mt < 4; mt++) {
        const int row0 = wm * 64 + mt * 16 + g;
        const int row1 = row0 + 8;
#pragma unroll
        for (int nt = 0; nt < 4; nt++) {
            const int col = wn * 32 + nt * 8 + 2 * tg;
            float c0 = acc[mt][nt][0], c1 = acc[mt][nt][1];
            float c2 = acc[mt][nt][2], c3 = acc[mt][nt][3];
            const float b0 = bias[j0 + col], b1 = bias[j0 + col + 1];
            c0 += b0; c1 += b1; c2 += b0; c3 += b1;
            c0 = (c0 > 0.f) ? c0 : 0.01f * c0;
            c1 = (c1 > 0.f) ? c1 : 0.01f * c1;
            c2 = (c2 > 0.f) ? c2 : 0.01f * c2;
            c3 = (c3 > 0.f) ? c3 : 0.01f * c3;
            bf16 h0, h1, h2, h3, l0, l1, l2, l3;
            split1(c0, h0, l0); split1(c1, h1, l1);
            split1(c2, h2, l2); split1(c3, h3, l3);
            *(uint32_t*)(Chi + (size_t)row0 * ldc + col) = pack2(h0, h1);
            *(uint32_t*)(Chi + (size_t)row1 * ldc + col) = pack2(h2, h3);
            *(uint32_t*)(Clo + (size_t)row0 * ldc + col) = pack2(l0, l1);
            *(uint32_t*)(Clo + (size_t)row1 * ldc + col) = pack2(l2, l3);
        }
    }
}

#define SM_MLP (2 * 4 * (128 * PITCH_B))    // 81920

__global__ __launch_bounds__(256, 2)
void k_mlp(const float* __restrict__ bhv, const float* __restrict__ bvv)
{
    const int nt = blockIdx.x, mt = blockIdx.y, which = blockIdx.z;
    const bf16* Ah = g_x_hi + (size_t)mt * 128 * IN_DIM;
    const bf16* Al = g_x_lo + (size_t)mt * 128 * IN_DIM;
    const bf16* Bh = g_Wm_hi + (size_t)which * BIAFF * IN_DIM + (size_t)nt * 128 * IN_DIM;
    const bf16* Bl = g_Wm_lo + (size_t)which * BIAFF * IN_DIM + (size_t)nt * 128 * IN_DIM;
    bf16* Oh = (which ? g_v_hi : g_h_hi) + (size_t)mt * 128 * BIAFF + nt * 128;
    bf16* Ol = (which ? g_v_lo : g_h_lo) + (size_t)mt * 128 * BIAFF + nt * 128;
    const float* bias = which ? bvv : bhv;

    run_tile<2>(Ah, Al, IN_DIM, Bh, Bl, IN_DIM, IN_DIM,
                Oh, Ol, BIAFF, bias, nt * 128);
}

// ---------------- phase A: h-resident, W streamed (trans LDSM) --------------
// CTA (b,l2,d,h): C[l,y] = sum_x h[l,x] * W[d,x,y]. A resident pitch 272.
#define P272      272
#define PA_ARES   (128u * P272)             // 34816
#define PA_BST    (32u * P272)              // 8704 per array
#define PA_SMEM   (2 * PA_ARES + 2 * 2 * PA_BST)   // 104448

__global__ __launch_bounds__(256, 2)
void k_phaseA()
{
    const int b  = blockIdx.x >> 1;
    const int l2 = blockIdx.x & 1;
    const int d  = blockIdx.y;
    const int h  = blockIdx.z;

    const bf16* Ahi = g_h_hi + ((size_t)(b * MAX_LEN + l2 * 128)) * BIAFF + h * HD;
    const bf16* Alo = g_h_lo + ((size_t)(b * MAX_LEN + l2 * 128)) * BIAFF + h * HD;
    const bf16* Bhi = g_W_hi + ((size_t)(h * HD + d)) * HD * HD;   // [x][y]
    const bf16* Blo = g_W_lo + ((size_t)(h * HD + d)) * HD * HD;
    bf16* Chi = g_T_hi + (((size_t)(b * NHEAD + h) * MAX_LEN + l2 * 128)) * (HD * HD)
                       + (size_t)d * HD;
    bf16* Clo = g_T_lo + (((size_t)(b * NHEAD + h) * MAX_LEN + l2 * 128)) * (HD * HD)
                       + (size_t)d * HD;
    const int ldc = HD * HD;

    extern __shared__ char smem[];
    const uint32_t sbase = smem_u32(smem);
    const uint32_t aResH = sbase, aResL = sbase + PA_ARES;
    const int tid  = threadIdx.x;
    const int lane = tid & 31;
    const int wid  = tid >> 5;
    const int wm   = wid >> 2;
    const int wn   = wid & 3;
    const int g    = lane >> 2;
    const int tg   = lane & 3;

    float acc[4][4][4];
#pragma unroll
    for (int a = 0; a < 4; a++)
#pragma unroll
        for (int bb = 0; bb < 4; bb++)
#pragma unroll
            for (int c = 0; c < 4; c++) acc[a][bb][c] = 0.0f;

    // group0: resident A (h tile), 128 rows x 256B, pitch 272
#pragma unroll
    for (int it = 0; it < 8; it++) {
        const int idx = tid + it * 256;
        const int r = idx >> 4, c16 = idx & 15;
        const uint32_t off = (uint32_t)r * P272 + c16 * 16;
        cp16(aResH + off, Ahi + (size_t)r * BIAFF + c16 * 8);
        cp16(aResL + off, Alo + (size_t)r * BIAFF + c16 * 8);
    }
    CP_COMMIT();

    auto load_B = [&](int c, int stage) {
        const uint32_t sb = sbase + 2 * PA_ARES + (uint32_t)stage * 2 * PA_BST;
#pragma unroll
        for (int it = 0; it < 2; it++) {
            const int idx = tid + it * 256;
            const int r = idx >> 4, c16 = idx & 15;
            const uint32_t off = (uint32_t)r * P272 + c16 * 16;
            cp16(sb + off, Bhi + (size_t)(c * 32 + r) * HD + c16 * 8);
            cp16(sb + PA_BST + off, Blo + (size_t)(c * 32 + r) * HD + c16 * 8);
        }
        CP_COMMIT();
    };
    load_B(0, 0);
    load_B(1, 1);

    const int lr   = lane & 15;
    const int lc16 = (lane >> 4) * 16;
    const int ycol = (lane >> 4) * 8;

#pragma unroll
    for (int c = 0; c < 4; c++) {
        if (c < 3) CP_WAIT1(); else CP_WAIT0();
        __syncthreads();

        const uint32_t sb = sbase + 2 * PA_ARES + (uint32_t)(c & 1) * 2 * PA_BST;
#pragma unroll
        for (int ks = 0; ks < 2; ks++) {
            uint32_t bh[8], bl[8];
#pragma unroll
            for (int half = 0; half < 2; half++) {
                const uint32_t addr = (uint32_t)(ks * 16 + lr) * P272
                                    + (uint32_t)(wn * 32 + half * 16 + ycol) * 2;
                LDSM_X4_T(&bh[half * 4], sb + addr);
                LDSM_X4_T(&bl[half * 4], sb + PA_BST + addr);
            }
#pragma unroll
            for (int mt = 0; mt < 4; mt++) {
                const uint32_t rowb = (uint32_t)(wm * 64 + mt * 16 + lr) * P272
                                    + c * 64 + ks * 32 + lc16;
                uint32_t ah[4], al[4];
                LDSM_X4(ah, aResH + rowb);
                LDSM_X4(al, aResL + rowb);
#pragma unroll
                for (int nt = 0; nt < 4; nt++) {
                    uint32_t Bh2[2] = { bh[nt * 2], bh[nt * 2 + 1] };
                    uint32_t Bl2[2] = { bl[nt * 2], bl[nt * 2 + 1] };
                    MMA_BF16(acc[mt][nt], ah, Bh2);
                    MMA_BF16(acc[mt][nt], ah, Bl2);
                    MMA_BF16(acc[mt][nt], al, Bh2);
                }
            }
        }
        __syncthreads();
        if (c + 2 < 4) load_B(c + 2, c & 1);
    }

#pragma unroll
    for (int mt = 0; mt < 4; mt++) {
        const int row0 = wm * 64 + mt * 16 + g;
        const int row1 = row0 + 8;
#pragma unroll
        for (int nt = 0; nt < 4; nt++) {
            const int col = wn * 32 + nt * 8 + 2 * tg;
            bf16 h0, h1, h2, h3, l0, l1, l2, l3;
            split1(acc[mt][nt][0], h0, l0); split1(acc[mt][nt][1], h1, l1);
            split1(acc[mt][nt][2], h2, l2); split1(acc[mt][nt][3], h3, l3);
            *(uint32_t*)(Chi + (size_t)row0 * ldc + col) = pack2(h0, h1);
            *(uint32_t*)(Chi + (size_t)row1 * ldc + col) = pack2(h2, h3);
            *(uint32_t*)(Clo + (size_t)row0 * ldc + col) = pack2(l0, l1);
            *(uint32_t*)(Clo + (size_t)row1 * ldc + col) = pack2(l2, l3);
        }
    }
}

// ---------------- phase B: T-resident, v streamed ---------------------------
// CTA (b,h,l): for k2 in {0,1}: out[k,d] = sum_y v[k2*128+k, y] * T[l][d][y]
#define PB_BRES   (128u * P272)             // 34816 per array
#define PB_AST    (128u * PITCH_B)          // 10240 per array
#define PB_SMEM   (2 * PB_BRES + 2 * 2 * PB_AST)    // 110592

__global__ __launch_bounds__(256, 2)
void k_phaseB(float* __restrict__ out)
{
    const int l = blockIdx.x;
    const int h = blockIdx.y, b = blockIdx.z;

    const bf16* Ahi = g_v_hi + (size_t)(b * MAX_LEN) * BIAFF + h * HD;
    const bf16* Alo = g_v_lo + (size_t)(b * MAX_LEN) * BIAFF + h * HD;
    const bf16* Bhi = g_T_hi + (((size_t)(b * NHEAD + h) * MAX_LEN + l)) * (HD * HD);
    const bf16* Blo = g_T_lo + (((size_t)(b * NHEAD + h) * MAX_LEN + l)) * (HD * HD);
    float* Cbase = out + (((size_t)(b * MAX_LEN + l) * MAX_LEN)) * OUTC + h * HD;

    extern __shared__ char smem[];
    const uint32_t sbase = smem_u32(smem);
    const uint32_t bResH = sbase, bResL = sbase + PB_BRES;
    const int tid  = threadIdx.x;
    const int lane = tid & 31;
    const int wid  = tid >> 5;
    const int wm   = wid >> 2;
    const int wn   = wid & 3;
    const int g    = lane >> 2;
    const int tg   = lane & 3;

    float acc[4][4][4];
#pragma unroll
    for (int a = 0; a < 4; a++)
#pragma unroll
        for (int bb = 0; bb < 4; bb++)
#pragma unroll
            for (int c = 0; c < 4; c++) acc[a][bb][c] = 0.0f;

    // group0: resident B = T[l], 128 d-rows x 256B, pitch 272
#pragma unroll
    for (int it = 0; it < 8; it++) {
        const int idx = tid + it * 256;
        const int r = idx >> 4, c16 = idx & 15;
        const uint32_t off = (uint32_t)r * P272 + c16 * 16;
        cp16(bResH + off, Bhi + (size_t)r * HD + c16 * 8);
        cp16(bResL + off, Blo + (size_t)r * HD + c16 * 8);
    }
    CP_COMMIT();

    auto load_A = [&](int c, int stage) {     // chunk c: k2 = c>>2, k-off (c&3)*32
        const uint32_t sb = sbase + 2 * PB_BRES + (uint32_t)stage * 2 * PB_AST;
        const int k2 = c >> 2, ko = (c & 3) * 32;
#pragma unroll
        for (int it = 0; it < 2; it++) {
            const int idx = tid + it * 256;
            const int r = idx >> 2, c4 = idx & 3;
            const uint32_t off = (uint32_t)r * PITCH_B + c4 * 16;
            const size_t src = (size_t)(k2 * 128 + r) * BIAFF + ko + c4 * 8;
            cp16(sb + off, Ahi + src);
            cp16(sb + PB_AST + off, Alo + src);
        }
        CP_COMMIT();
    };
    load_A(0, 0);
    load_A(1, 1);

    const int lr   = lane & 15;
    const int lc16 = (lane >> 4) * 16;

#pragma unroll
    for (int c = 0; c < 8; c++) {
        if (c < 7) CP_WAIT1(); else CP_WAIT0();
        __syncthreads();

        const uint32_t sb = sbase + 2 * PB_BRES + (uint32_t)(c & 1) * 2 * PB_AST;
        const int kbase = (c & 3) * 32;
#pragma unroll
        for (int ks = 0; ks < 2; ks++) {
            uint32_t bh[8], bl[8];
#pragma unroll
            for (int np = 0; np < 2; np++) {
                const uint32_t rowb = (uint32_t)(wn * 32 + np * 16 + lr) * P272
                                    + kbase * 2 + ks * 32 + lc16;
                LDSM_X4(&bh[np * 4], bResH + rowb);
                LDSM_X4(&bl[np * 4], bResL + rowb);
            }
#pragma unroll
            for (int mt = 0; mt < 4; mt++) {
                const uint32_t rowb = (uint32_t)(wm * 64 + mt * 16 + lr) * PITCH_B
                                    + ks * 32 + lc16;
                uint32_t ah[4], al[4];
                LDSM_X4(ah, sb + rowb);
                LDSM_X4(al, sb + PB_AST + rowb);
#pragma unroll
                for (int nt = 0; nt < 4; nt++) {
                    uint32_t Bh2[2] = { bh[(nt >> 1) * 4 + (nt & 1)],
                                        bh[(nt >> 1) * 4 + 2 + (nt & 1)] };
                    uint32_t Bl2[2] = { bl[(nt >> 1) * 4 + (nt & 1)],
                                        bl[(nt >> 1) * 4 + 2 + (nt & 1)] };
                    MMA_BF16(acc[mt][nt], ah, Bh2);
                    MMA_BF16(acc[mt][nt], ah, Bl2);
                    MMA_BF16(acc[mt][nt], al, Bh2);
                }
            }
        }
        __syncthreads();
        if (c + 2 < 8) load_A(c + 2, c & 1);

        if ((c & 3) == 3) {           // end of one k2: store + reset acc
            float* Cf = Cbase + (size_t)(c >> 2) * 128 * OUTC;
#pragma unroll
            for (int mt = 0; mt < 4; mt++) {
                const int row0 = wm * 64 + mt * 16 + g;
                const int row1 = row0 + 8;
#pragma unroll
                for (int nt = 0; nt < 4; nt++) {
                    const int col = wn * 32 + nt * 8 + 2 * tg;
                    *(float2*)(Cf + (size_t)row0 * OUTC + col) =
                        make_float2(acc[mt][nt][0], acc[mt][nt][1]);
                    *(float2*)(Cf + (size_t)row1 * OUTC + col) =
                        make_float2(acc[mt][nt][2], acc[mt][nt][3]);
                    acc[mt][nt][0] = acc[mt][nt][1] = 0.0f;
                    acc[mt][nt][2] = acc[mt][nt][3] = 0.0f;
                }
            }
        }
    }
}

// ---------------------------------------------------------------------------
extern "C" void kernel_launch(void* const* d_in, const int* in_sizes, int n_in,
                              void* d_out, int out_size)
{
    const float* x  = (const float*)d_in[0];
    const float* Wh = (const float*)d_in[1];
    const float* bh = (const float*)d_in[2];
    const float* Wv = (const float*)d_in[3];
    const float* bv = (const float*)d_in[4];
    const float* W  = (const float*)d_in[5];
    float* out = (float*)d_out;

    cudaFuncSetAttribute(k_mlp,    cudaFuncAttributeMaxDynamicSharedMemorySize, SM_MLP);
    cudaFuncSetAttribute(k_phaseA, cudaFuncAttributeMaxDynamicSharedMemorySize, PA_SMEM);
    cudaFuncSetAttribute(k_phaseB, cudaFuncAttributeMaxDynamicSharedMemorySize, PB_SMEM);

    k_prep  <<<4096, 256>>>(x, Wh, Wv, W);
    k_mlp   <<<dim3(4,   8, 2), 256, SM_MLP>>>(bh, bv);
    k_phaseA<<<dim3(8, 128, 4), 256, PA_SMEM>>>();
    k_phaseB<<<dim3(256, 4, 4), 256, PB_SMEM>>>(out);

    (void)in_sizes; (void)n_in; (void)out_size;
}